// round 11
// baseline (speedup 1.0000x reference)
#include <cuda_runtime.h>
#include <cstdint>
#include <cstddef>

#define B_  2
#define S_  8192
#define D_  1024
#define H_  16
#define HD_ 64
#define A_  1024
#define SQ_ (S_ - A_)   // 7168

// Scratch (allocation-free rule: __device__ globals)
__device__ float g_Q[(size_t)B_ * H_ * S_ * HD_];   // [b,h,s,d]  64 MB
__device__ float g_K[(size_t)B_ * H_ * A_ * HD_];   // [b,h,a,d]   8 MB
__device__ float g_V[(size_t)B_ * H_ * A_ * HD_];   //             8 MB
__device__ float g_AO[(size_t)B_ * S_ * D_];        // [b,s,h*hd+d] 64 MB

// ---------------------------------------------------------------------------
// Tiled SGEMM: 128x128 block tile, K-tile 16, 256 threads, 8x8 per-thread.
// MODE 0: anchors @ Wqkv (+bqkv) -> scatter into g_Q (anchor rows) / g_K / g_V
// MODE 1: queries @ Wq   (+bq)   -> scatter into g_Q (query rows)
// MODE 2: g_AO @ Wproj   (+bproj)-> d_out
// ---------------------------------------------------------------------------
template <int MODE>
__global__ __launch_bounds__(256, 2) void gemm_kernel(
    const float* __restrict__ Ain, const float* __restrict__ Bw,
    const float* __restrict__ bias, float* __restrict__ Cout)
{
    constexpr int NN = (MODE == 0) ? 3 * D_ : D_;

    __shared__ float As[16][132];   // transposed A tile, padded
    __shared__ float Bs[16][128];

    const int tid = threadIdx.x;
    const int tx = tid & 15;
    const int ty = tid >> 4;
    const int rm0 = blockIdx.y * 128;
    const int cn0 = blockIdx.x * 128;

    // A-tile load mapping: m = tid/4 (+64), k0 = (tid%4)*4
    const int a_m = tid >> 2;
    const int a_k = (tid & 3) << 2;

    auto arowptr = [&](int m) -> const float* {
        int r = rm0 + m;
        if constexpr (MODE == 0) {
            int b = r >> 10, s = r & (A_ - 1);
            return Ain + (size_t)(b * S_ + s) * D_;
        } else if constexpr (MODE == 1) {
            int b = r / SQ_, s = r - b * SQ_;
            return Ain + (size_t)(b * S_ + A_ + s) * D_;
        } else {
            return g_AO + (size_t)r * D_;
        }
    };
    const float* arow0 = arowptr(a_m);
    const float* arow1 = arowptr(a_m + 64);

    // B-tile load mapping: k = tid/32 (+8), col = (tid%32)*4
    const int b_k = tid >> 5;
    const int b_c = (tid & 31) << 2;
    const float* bptr = Bw + (size_t)b_k * NN + cn0 + b_c;

    float acc[8][8];
#pragma unroll
    for (int i = 0; i < 8; i++)
#pragma unroll
        for (int j = 0; j < 8; j++) acc[i][j] = 0.f;

#pragma unroll 1
    for (int kt = 0; kt < D_ / 16; ++kt) {
        const int kg = kt << 4;
        float4 av0 = *(const float4*)(arow0 + kg + a_k);
        float4 av1 = *(const float4*)(arow1 + kg + a_k);
        float4 bv0 = *(const float4*)(bptr + (size_t)kg * NN);
        float4 bv1 = *(const float4*)(bptr + (size_t)(kg + 8) * NN);

        __syncthreads();
        As[a_k + 0][a_m] = av0.x; As[a_k + 1][a_m] = av0.y;
        As[a_k + 2][a_m] = av0.z; As[a_k + 3][a_m] = av0.w;
        As[a_k + 0][a_m + 64] = av1.x; As[a_k + 1][a_m + 64] = av1.y;
        As[a_k + 2][a_m + 64] = av1.z; As[a_k + 3][a_m + 64] = av1.w;
        *(float4*)&Bs[b_k][b_c]     = bv0;
        *(float4*)&Bs[b_k + 8][b_c] = bv1;
        __syncthreads();

#pragma unroll
        for (int kk = 0; kk < 16; ++kk) {
            float4 af0 = *(const float4*)&As[kk][ty << 3];
            float4 af1 = *(const float4*)&As[kk][(ty << 3) + 4];
            float4 bf0 = *(const float4*)&Bs[kk][tx << 3];
            float4 bf1 = *(const float4*)&Bs[kk][(tx << 3) + 4];
            float a_[8] = {af0.x, af0.y, af0.z, af0.w, af1.x, af1.y, af1.z, af1.w};
            float b_[8] = {bf0.x, bf0.y, bf0.z, bf0.w, bf1.x, bf1.y, bf1.z, bf1.w};
#pragma unroll
            for (int i = 0; i < 8; i++)
#pragma unroll
                for (int j = 0; j < 8; j++) acc[i][j] += a_[i] * b_[j];
        }
    }

    // Epilogue with bias + scatter
    const int ccol = cn0 + (tx << 3);
    float bia[8];
#pragma unroll
    for (int j = 0; j < 8; j++) bia[j] = bias[ccol + j];

#pragma unroll
    for (int i = 0; i < 8; i++) {
        int r = rm0 + (ty << 3) + i;
        float v[8];
#pragma unroll
        for (int j = 0; j < 8; j++) v[j] = acc[i][j] + bia[j];

        float* dst;
        if constexpr (MODE == 0) {
            int b = r >> 10, s = r & (A_ - 1);
            int three = ccol >> 10;
            int rem = ccol & 1023;
            int h = rem >> 6, d = rem & 63;
            if (three == 0)
                dst = g_Q + ((size_t)(b * H_ + h) * S_ + s) * HD_ + d;
            else if (three == 1)
                dst = g_K + ((size_t)(b * H_ + h) * A_ + s) * HD_ + d;
            else
                dst = g_V + ((size_t)(b * H_ + h) * A_ + s) * HD_ + d;
        } else if constexpr (MODE == 1) {
            int b = r / SQ_, s = r - b * SQ_;
            int h = ccol >> 6, d = ccol & 63;
            dst = g_Q + ((size_t)(b * H_ + h) * S_ + (A_ + s)) * HD_ + d;
        } else {
            dst = Cout + (size_t)r * D_ + ccol;
        }
        *(float4*)(dst)     = make_float4(v[0], v[1], v[2], v[3]);
        *(float4*)(dst + 4) = make_float4(v[4], v[5], v[6], v[7]);
    }
}

// ---------------------------------------------------------------------------
// Flash attention: 64 queries/block, 256 threads (4 threads per query),
// key tiles of 64, online softmax. K smem buffer is reused for P (scores).
// ---------------------------------------------------------------------------
__global__ __launch_bounds__(256, 2) void attn_kernel()
{
    __shared__ float KPs[64][68];   // K tile, then P tile (aliased)
    __shared__ float Vs[64][68];

    const int tid = threadIdx.x;
    const int tq = tid >> 2;        // query index in block (0..63)
    const int l4 = tid & 3;         // 4-thread group within a query
    const int b = blockIdx.z, h = blockIdx.y;
    const int bh = b * H_ + h;
    const int q0 = blockIdx.x * 64;

    const float scale = 0.125f;     // 1/sqrt(64)

    // Q row into registers, pre-scaled (redundant across the 4-thread group)
    const float* qrow = g_Q + ((size_t)bh * S_ + q0 + tq) * HD_;
    float qreg[64];
#pragma unroll
    for (int d4 = 0; d4 < 16; ++d4) {
        float4 qv = ((const float4*)qrow)[d4];
        qreg[4 * d4 + 0] = qv.x * scale;
        qreg[4 * d4 + 1] = qv.y * scale;
        qreg[4 * d4 + 2] = qv.z * scale;
        qreg[4 * d4 + 3] = qv.w * scale;
    }

    const float* Kb = g_K + (size_t)bh * A_ * HD_;
    const float* Vb = g_V + (size_t)bh * A_ * HD_;

    float acc[16];
#pragma unroll
    for (int j = 0; j < 16; j++) acc[j] = 0.f;
    float mrun = -1e30f, lrun = 0.f;

#pragma unroll 1
    for (int kt = 0; kt < A_ / 64; ++kt) {
        const float* Kt = Kb + (size_t)kt * 64 * HD_;
        const float* Vt = Vb + (size_t)kt * 64 * HD_;

        __syncthreads();   // previous iteration's P/V reads are done
#pragma unroll
        for (int j = 0; j < 4; ++j) {
            int idx = j * 256 + tid;        // 0..1023
            int row = idx >> 4;
            int c = (idx & 15) << 2;
            float4 kv = *(const float4*)(Kt + row * HD_ + c);
            float4 vv = *(const float4*)(Vt + row * HD_ + c);
            *(float4*)&KPs[row][c] = kv;
            *(float4*)&Vs[row][c]  = vv;
        }
        __syncthreads();

        // scores: this thread owns keys k = 4*i + l4
        float s[16];
#pragma unroll
        for (int i = 0; i < 16; ++i) {
            int k = (i << 2) + l4;
            const float4* k4 = (const float4*)&KPs[k][0];
            float sum = 0.f;
#pragma unroll
            for (int d4 = 0; d4 < 16; ++d4) {
                float4 kv = k4[d4];
                sum += qreg[4 * d4 + 0] * kv.x + qreg[4 * d4 + 1] * kv.y
                     + qreg[4 * d4 + 2] * kv.z + qreg[4 * d4 + 3] * kv.w;
            }
            s[i] = sum;
        }

        // online softmax (reduce across the 4-thread group; lanes are aligned)
        float tmax = s[0];
#pragma unroll
        for (int i = 1; i < 16; ++i) tmax = fmaxf(tmax, s[i]);
        tmax = fmaxf(tmax, __shfl_xor_sync(0xffffffffu, tmax, 1));
        tmax = fmaxf(tmax, __shfl_xor_sync(0xffffffffu, tmax, 2));
        float mnew = fmaxf(mrun, tmax);
        float corr = __expf(mrun - mnew);
        float lsum = 0.f;
#pragma unroll
        for (int i = 0; i < 16; ++i) { float p = __expf(s[i] - mnew); s[i] = p; lsum += p; }
        lsum += __shfl_xor_sync(0xffffffffu, lsum, 1);
        lsum += __shfl_xor_sync(0xffffffffu, lsum, 2);
        lrun = lrun * corr + lsum;
        mrun = mnew;
#pragma unroll
        for (int j = 0; j < 16; j++) acc[j] *= corr;

        __syncthreads();   // everyone done reading KPs as K
#pragma unroll
        for (int i = 0; i < 16; ++i) KPs[tq][(i << 2) + l4] = s[i];
        __syncthreads();

        // PV: this thread owns output dims d = 16*l4 .. 16*l4+15
#pragma unroll 16
        for (int kk = 0; kk < 64; ++kk) {
            float p = KPs[tq][kk];
            const float4* v4 = (const float4*)&Vs[kk][l4 << 4];
            float4 v0 = v4[0], v1 = v4[1], v2 = v4[2], v3 = v4[3];
            acc[0]  += p * v0.x; acc[1]  += p * v0.y; acc[2]  += p * v0.z; acc[3]  += p * v0.w;
            acc[4]  += p * v1.x; acc[5]  += p * v1.y; acc[6]  += p * v1.z; acc[7]  += p * v1.w;
            acc[8]  += p * v2.x; acc[9]  += p * v2.y; acc[10] += p * v2.z; acc[11] += p * v2.w;
            acc[12] += p * v3.x; acc[13] += p * v3.y; acc[14] += p * v3.z; acc[15] += p * v3.w;
        }
    }

    const float linv = 1.f / lrun;
    float* dst = g_AO + (size_t)(b * S_ + q0 + tq) * D_ + h * HD_ + (l4 << 4);
#pragma unroll
    for (int j4 = 0; j4 < 4; ++j4) {
        float4 o = make_float4(acc[4 * j4 + 0] * linv, acc[4 * j4 + 1] * linv,
                               acc[4 * j4 + 2] * linv, acc[4 * j4 + 3] * linv);
        *(float4*)(dst + 4 * j4) = o;
    }
}

// ---------------------------------------------------------------------------
extern "C" void kernel_launch(void* const* d_in, const int* in_sizes, int n_in,
                              void* d_out, int out_size)
{
    const float* x     = (const float*)d_in[0];
    const float* Wqkv  = (const float*)d_in[1];
    const float* bqkv  = (const float*)d_in[2];
    const float* Wq    = (const float*)d_in[3];
    const float* bq    = (const float*)d_in[4];
    const float* Wproj = (const float*)d_in[5];
    const float* bproj = (const float*)d_in[6];
    float* out = (float*)d_out;

    dim3 blk(256);
    // anchors @ Wqkv : M = B*A = 2048, N = 3072
    gemm_kernel<0><<<dim3(3 * D_ / 128, (B_ * A_) / 128), blk>>>(x, Wqkv, bqkv, nullptr);
    // queries @ Wq : M = B*SQ = 14336, N = 1024
    gemm_kernel<1><<<dim3(D_ / 128, (B_ * SQ_) / 128), blk>>>(x, Wq, bq, nullptr);
    // attention: grid (S/64, H, B) = (128, 16, 2)
    attn_kernel<<<dim3(S_ / 64, H_, B_), blk>>>();
    // g_AO @ Wproj : M = B*S = 16384, N = 1024
    gemm_kernel<2><<<dim3(D_ / 128, (B_ * S_) / 128), blk>>>(x, Wproj, bproj, out);
}

// round 12
// speedup vs baseline: 2.1775x; 2.1775x over previous
#include <cuda_runtime.h>
#include <cstdint>
#include <cstddef>

#define B_  2
#define S_  8192
#define D_  1024
#define H_  16
#define HD_ 64
#define A_  1024
#define SQ_ (S_ - A_)   // 7168

// Scratch (allocation-free rule: __device__ globals)
__device__ float g_Q[(size_t)B_ * H_ * S_ * HD_];   // [b,h,s,d]  64 MB
__device__ float g_K[(size_t)B_ * H_ * A_ * HD_];   // [b,h,a,d]   8 MB
__device__ float g_V[(size_t)B_ * H_ * A_ * HD_];   //             8 MB
__device__ float g_AO[(size_t)B_ * S_ * D_];        // [b,s,h*hd+d] 64 MB

// ---------------------------------------------------------------------------
// Tiled SGEMM: 128x128 block tile, K-tile 16, 256 threads, 8x8 per-thread.
// MODE 0: anchors @ Wqkv (+bqkv) -> scatter into g_Q (anchor rows) / g_K / g_V
// MODE 1: queries @ Wq   (+bq)   -> scatter into g_Q (query rows)
// MODE 2: g_AO @ Wproj   (+bproj)-> d_out
// ---------------------------------------------------------------------------
template <int MODE>
__global__ __launch_bounds__(256, 2) void gemm_kernel(
    const float* __restrict__ Ain, const float* __restrict__ Bw,
    const float* __restrict__ bias, float* __restrict__ Cout)
{
    constexpr int NN = (MODE == 0) ? 3 * D_ : D_;

    __shared__ float As[16][132];   // transposed A tile, padded
    __shared__ float Bs[16][128];

    const int tid = threadIdx.x;
    const int tx = tid & 15;
    const int ty = tid >> 4;
    const int rm0 = blockIdx.y * 128;
    const int cn0 = blockIdx.x * 128;

    // A-tile load mapping: m = tid/4 (+64), k0 = (tid%4)*4
    const int a_m = tid >> 2;
    const int a_k = (tid & 3) << 2;

    auto arowptr = [&](int m) -> const float* {
        int r = rm0 + m;
        if constexpr (MODE == 0) {
            int b = r >> 10, s = r & (A_ - 1);
            return Ain + (size_t)(b * S_ + s) * D_;
        } else if constexpr (MODE == 1) {
            int b = r / SQ_, s = r - b * SQ_;
            return Ain + (size_t)(b * S_ + A_ + s) * D_;
        } else {
            return g_AO + (size_t)r * D_;
        }
    };
    const float* arow0 = arowptr(a_m);
    const float* arow1 = arowptr(a_m + 64);

    // B-tile load mapping: k = tid/32 (+8), col = (tid%32)*4
    const int b_k = tid >> 5;
    const int b_c = (tid & 31) << 2;
    const float* bptr = Bw + (size_t)b_k * NN + cn0 + b_c;

    float acc[8][8];
#pragma unroll
    for (int i = 0; i < 8; i++)
#pragma unroll
        for (int j = 0; j < 8; j++) acc[i][j] = 0.f;

#pragma unroll 1
    for (int kt = 0; kt < D_ / 16; ++kt) {
        const int kg = kt << 4;
        float4 av0 = *(const float4*)(arow0 + kg + a_k);
        float4 av1 = *(const float4*)(arow1 + kg + a_k);
        float4 bv0 = *(const float4*)(bptr + (size_t)kg * NN);
        float4 bv1 = *(const float4*)(bptr + (size_t)(kg + 8) * NN);

        __syncthreads();
        As[a_k + 0][a_m] = av0.x; As[a_k + 1][a_m] = av0.y;
        As[a_k + 2][a_m] = av0.z; As[a_k + 3][a_m] = av0.w;
        As[a_k + 0][a_m + 64] = av1.x; As[a_k + 1][a_m + 64] = av1.y;
        As[a_k + 2][a_m + 64] = av1.z; As[a_k + 3][a_m + 64] = av1.w;
        *(float4*)&Bs[b_k][b_c]     = bv0;
        *(float4*)&Bs[b_k + 8][b_c] = bv1;
        __syncthreads();

#pragma unroll
        for (int kk = 0; kk < 16; ++kk) {
            float4 af0 = *(const float4*)&As[kk][ty << 3];
            float4 af1 = *(const float4*)&As[kk][(ty << 3) + 4];
            float4 bf0 = *(const float4*)&Bs[kk][tx << 3];
            float4 bf1 = *(const float4*)&Bs[kk][(tx << 3) + 4];
            float a_[8] = {af0.x, af0.y, af0.z, af0.w, af1.x, af1.y, af1.z, af1.w};
            float b_[8] = {bf0.x, bf0.y, bf0.z, bf0.w, bf1.x, bf1.y, bf1.z, bf1.w};
#pragma unroll
            for (int i = 0; i < 8; i++)
#pragma unroll
                for (int j = 0; j < 8; j++) acc[i][j] += a_[i] * b_[j];
        }
    }

    // Epilogue with bias + scatter
    const int ccol = cn0 + (tx << 3);
    float bia[8];
#pragma unroll
    for (int j = 0; j < 8; j++) bia[j] = bias[ccol + j];

#pragma unroll
    for (int i = 0; i < 8; i++) {
        int r = rm0 + (ty << 3) + i;
        float v[8];
#pragma unroll
        for (int j = 0; j < 8; j++) v[j] = acc[i][j] + bia[j];

        float* dst;
        if constexpr (MODE == 0) {
            int b = r >> 10, s = r & (A_ - 1);
            int three = ccol >> 10;
            int rem = ccol & 1023;
            int h = rem >> 6, d = rem & 63;
            if (three == 0)
                dst = g_Q + ((size_t)(b * H_ + h) * S_ + s) * HD_ + d;
            else if (three == 1)
                dst = g_K + ((size_t)(b * H_ + h) * A_ + s) * HD_ + d;
            else
                dst = g_V + ((size_t)(b * H_ + h) * A_ + s) * HD_ + d;
        } else if constexpr (MODE == 1) {
            int b = r / SQ_, s = r - b * SQ_;
            int h = ccol >> 6, d = ccol & 63;
            dst = g_Q + ((size_t)(b * H_ + h) * S_ + (A_ + s)) * HD_ + d;
        } else {
            dst = Cout + (size_t)r * D_ + ccol;
        }
        *(float4*)(dst)     = make_float4(v[0], v[1], v[2], v[3]);
        *(float4*)(dst + 4) = make_float4(v[4], v[5], v[6], v[7]);
    }
}

// ---------------------------------------------------------------------------
// Flash attention v2: register-blocked like the SGEMM.
// 128 queries/block, 256 threads (16x16), key tiles of 64.
// Thread (ty,tx): S-tile rows q=ty*8+i (i<8), cols k=tx*4+j (j<4);
//                 O-tile rows q=ty*8+i,        cols d=tx*4+j.
// m/l state register-replicated across the 16-lane row group (shfl_xor).
// Dynamic smem (101 KB): Qst[d][q] (transposed, pre-scaled), Kst[d][k]
// (transposed), Vs[k][d], Pst[q][k].
// ---------------------------------------------------------------------------
#define QST_STRIDE 132
#define KST_STRIDE 68
#define ATTN_SMEM_FLOATS (64 * QST_STRIDE + 64 * KST_STRIDE + 64 * KST_STRIDE + 128 * KST_STRIDE)
#define ATTN_SMEM_BYTES  (ATTN_SMEM_FLOATS * 4)

__global__ __launch_bounds__(256, 2) void attn_kernel()
{
    extern __shared__ float sm[];
    float* Qst = sm;                                 // [64][132]  (d, q)
    float* Kst = Qst + 64 * QST_STRIDE;              // [64][68]   (d, k)
    float* Vs  = Kst + 64 * KST_STRIDE;              // [64][68]   (k, d)
    float* Pst = Vs  + 64 * KST_STRIDE;              // [128][68]  (q, k)

    const int tid = threadIdx.x;
    const int tx = tid & 15;
    const int ty = tid >> 4;
    const int b = blockIdx.z, h = blockIdx.y;
    const int bh = b * H_ + h;
    const int q0 = blockIdx.x * 128;

    const float* Qg = g_Q + ((size_t)bh * S_ + q0) * HD_;
    const float* Kb = g_K + (size_t)bh * A_ * HD_;
    const float* Vb = g_V + (size_t)bh * A_ * HD_;

    // Load Q tile transposed into smem, pre-scaled by 1/sqrt(hd)
#pragma unroll
    for (int j = 0; j < 8; ++j) {
        int idx = j * 256 + tid;          // 0..2047 float4s
        int row = idx >> 4;               // q 0..127
        int dg  = idx & 15;               // d group
        float4 v = ((const float4*)(Qg + (size_t)row * HD_))[dg];
        Qst[(4 * dg + 0) * QST_STRIDE + row] = v.x * 0.125f;
        Qst[(4 * dg + 1) * QST_STRIDE + row] = v.y * 0.125f;
        Qst[(4 * dg + 2) * QST_STRIDE + row] = v.z * 0.125f;
        Qst[(4 * dg + 3) * QST_STRIDE + row] = v.w * 0.125f;
    }

    float acc[8][4];
#pragma unroll
    for (int i = 0; i < 8; i++)
#pragma unroll
        for (int j = 0; j < 4; j++) acc[i][j] = 0.f;
    float mrow[8], lrow[8];
#pragma unroll
    for (int i = 0; i < 8; i++) { mrow[i] = -1e30f; lrow[i] = 0.f; }

#pragma unroll 1
    for (int kt = 0; kt < A_ / 64; ++kt) {
        const float* Kt = Kb + (size_t)kt * 64 * HD_;
        const float* Vt = Vb + (size_t)kt * 64 * HD_;

        __syncthreads();   // previous tile's Kst/Vs/Pst reads done
#pragma unroll
        for (int j = 0; j < 4; ++j) {
            int idx = j * 256 + tid;      // 0..1023 float4s
            int row = idx >> 4;           // k 0..63
            int dg  = idx & 15;
            float4 kv = ((const float4*)(Kt + (size_t)row * HD_))[dg];
            Kst[(4 * dg + 0) * KST_STRIDE + row] = kv.x;
            Kst[(4 * dg + 1) * KST_STRIDE + row] = kv.y;
            Kst[(4 * dg + 2) * KST_STRIDE + row] = kv.z;
            Kst[(4 * dg + 3) * KST_STRIDE + row] = kv.w;
            float4 vv = ((const float4*)(Vt + (size_t)row * HD_))[dg];
            *(float4*)&Vs[row * KST_STRIDE + 4 * dg] = vv;
        }
        __syncthreads();

        // S = (Q*scale) . K^T  : 8x4 per thread, k-dim = hd = 64
        float s[8][4];
#pragma unroll
        for (int i = 0; i < 8; i++)
#pragma unroll
            for (int j = 0; j < 4; j++) s[i][j] = 0.f;

#pragma unroll
        for (int d = 0; d < 64; ++d) {
            float4 a0 = *(const float4*)&Qst[d * QST_STRIDE + (ty << 3)];
            float4 a1 = *(const float4*)&Qst[d * QST_STRIDE + (ty << 3) + 4];
            float4 bv = *(const float4*)&Kst[d * KST_STRIDE + (tx << 2)];
            float a_[8] = {a0.x, a0.y, a0.z, a0.w, a1.x, a1.y, a1.z, a1.w};
            float b_[4] = {bv.x, bv.y, bv.z, bv.w};
#pragma unroll
            for (int i = 0; i < 8; i++)
#pragma unroll
                for (int j = 0; j < 4; j++) s[i][j] += a_[i] * b_[j];
        }

        // Online softmax per row; reduce across the 16-lane row group.
#pragma unroll
        for (int i = 0; i < 8; ++i) {
            float tm = fmaxf(fmaxf(s[i][0], s[i][1]), fmaxf(s[i][2], s[i][3]));
            tm = fmaxf(tm, __shfl_xor_sync(0xffffffffu, tm, 1));
            tm = fmaxf(tm, __shfl_xor_sync(0xffffffffu, tm, 2));
            tm = fmaxf(tm, __shfl_xor_sync(0xffffffffu, tm, 4));
            tm = fmaxf(tm, __shfl_xor_sync(0xffffffffu, tm, 8));
            float mn = fmaxf(mrow[i], tm);
            float corr = __expf(mrow[i] - mn);
            mrow[i] = mn;
            float ls = 0.f;
#pragma unroll
            for (int j = 0; j < 4; ++j) {
                float p = __expf(s[i][j] - mn);
                s[i][j] = p;
                ls += p;
            }
            ls += __shfl_xor_sync(0xffffffffu, ls, 1);
            ls += __shfl_xor_sync(0xffffffffu, ls, 2);
            ls += __shfl_xor_sync(0xffffffffu, ls, 4);
            ls += __shfl_xor_sync(0xffffffffu, ls, 8);
            lrow[i] = lrow[i] * corr + ls;
#pragma unroll
            for (int j = 0; j < 4; ++j) acc[i][j] *= corr;
        }

        // P to smem (rows = this thread's q rows, cols = its k cols)
#pragma unroll
        for (int i = 0; i < 8; ++i)
            *(float4*)&Pst[((ty << 3) + i) * KST_STRIDE + (tx << 2)] =
                make_float4(s[i][0], s[i][1], s[i][2], s[i][3]);
        __syncthreads();

        // O += P . V : 8x4 per thread, k-dim = 64, unrolled by 4
#pragma unroll
        for (int k4 = 0; k4 < 16; ++k4) {
            float4 v0 = *(const float4*)&Vs[(k4 * 4 + 0) * KST_STRIDE + (tx << 2)];
            float4 v1 = *(const float4*)&Vs[(k4 * 4 + 1) * KST_STRIDE + (tx << 2)];
            float4 v2 = *(const float4*)&Vs[(k4 * 4 + 2) * KST_STRIDE + (tx << 2)];
            float4 v3 = *(const float4*)&Vs[(k4 * 4 + 3) * KST_STRIDE + (tx << 2)];
#pragma unroll
            for (int i = 0; i < 8; ++i) {
                float4 pv = *(const float4*)&Pst[((ty << 3) + i) * KST_STRIDE + k4 * 4];
                acc[i][0] += pv.x * v0.x + pv.y * v1.x + pv.z * v2.x + pv.w * v3.x;
                acc[i][1] += pv.x * v0.y + pv.y * v1.y + pv.z * v2.y + pv.w * v3.y;
                acc[i][2] += pv.x * v0.z + pv.y * v1.z + pv.z * v2.z + pv.w * v3.z;
                acc[i][3] += pv.x * v0.w + pv.y * v1.w + pv.z * v2.w + pv.w * v3.w;
            }
        }
    }

    // Epilogue: normalize and write [b, s, h*64 + d]
#pragma unroll
    for (int i = 0; i < 8; ++i) {
        float inv = 1.f / lrow[i];
        float* dst = g_AO + (size_t)(b * S_ + q0 + (ty << 3) + i) * D_
                   + h * HD_ + (tx << 2);
        *(float4*)dst = make_float4(acc[i][0] * inv, acc[i][1] * inv,
                                    acc[i][2] * inv, acc[i][3] * inv);
    }
}

// ---------------------------------------------------------------------------
extern "C" void kernel_launch(void* const* d_in, const int* in_sizes, int n_in,
                              void* d_out, int out_size)
{
    const float* x     = (const float*)d_in[0];
    const float* Wqkv  = (const float*)d_in[1];
    const float* bqkv  = (const float*)d_in[2];
    const float* Wq    = (const float*)d_in[3];
    const float* bq    = (const float*)d_in[4];
    const float* Wproj = (const float*)d_in[5];
    const float* bproj = (const float*)d_in[6];
    float* out = (float*)d_out;

    cudaFuncSetAttribute(attn_kernel,
                         cudaFuncAttributeMaxDynamicSharedMemorySize,
                         ATTN_SMEM_BYTES);

    dim3 blk(256);
    // anchors @ Wqkv : M = B*A = 2048, N = 3072
    gemm_kernel<0><<<dim3(3 * D_ / 128, (B_ * A_) / 128), blk>>>(x, Wqkv, bqkv, nullptr);
    // queries @ Wq : M = B*SQ = 14336, N = 1024
    gemm_kernel<1><<<dim3(D_ / 128, (B_ * SQ_) / 128), blk>>>(x, Wq, bq, nullptr);
    // attention: grid (S/128, H, B) = (64, 16, 2)
    attn_kernel<<<dim3(S_ / 128, H_, B_), blk, ATTN_SMEM_BYTES>>>();
    // g_AO @ Wproj : M = B*S = 16384, N = 1024
    gemm_kernel<2><<<dim3(D_ / 128, (B_ * S_) / 128), blk>>>(x, Wproj, bproj, out);
}